// round 5
// baseline (speedup 1.0000x reference)
#include <cuda_runtime.h>

// ---------------------------------------------------------------------------
// EfficientAttention, f32x2 packed-FMA, M=128-per-block version.
// N=2, D=64, H=W=64, C=64, HEADS=8, hk=hv=8. token = c*4096 + h*64 + w.
// Block handles TWO (h,w) positions (half = t>>6), 128 threads, 8x8 tiles.
// Staged matrices: row stride 64 floats, element e of row r at offset
// e ^ swk(r), swk(r) = ((r&7)^(r>>3))<<2  (conflict-free for all patterns).
// ---------------------------------------------------------------------------

#define T_TOK 262144
#define PLANE 262144
typedef unsigned long long u64t;

__device__ float g_Q[(size_t)2 * T_TOK * 64];   // 128 MiB scratch
__device__ float g_WT[4 * 4096];                // WqT, WkT, WvT, WrT
__device__ float g_ctxnum[2 * 512];
__device__ float g_den[2 * 64];

#define FMA2(acc, a, b) asm("fma.rn.f32x2 %0, %1, %2, %0;" : "+l"(acc) : "l"(a), "l"(b))

__device__ __forceinline__ float lrelu(float y) { return y >= 0.f ? y : 0.2f * y; }
__device__ __forceinline__ float2 unpk(u64t p) {
    float2 r; asm("mov.b64 {%0, %1}, %2;" : "=f"(r.x), "=f"(r.y) : "l"(p)); return r;
}
__device__ __forceinline__ u64t pk2(float lo, float hi) {
    u64t r; asm("mov.b64 %0, {%1, %2};" : "=l"(r) : "f"(lo), "f"(hi)); return r;
}
__device__ __forceinline__ int swk(int r) { return ((r & 7) ^ (r >> 3)) << 2; }

__global__ void setup_kernel(const float* __restrict__ Wq, const float* __restrict__ Wk,
                             const float* __restrict__ Wv, const float* __restrict__ Wr) {
    int t = threadIdx.x, b = blockIdx.x;
    const float* W = (b == 0) ? Wq : (b == 1) ? Wk : (b == 2) ? Wv : Wr;
    float* dst = g_WT + b * 4096;
    for (int idx = t; idx < 4096; idx += 256)
        dst[(idx & 63) * 64 + (idx >> 6)] = W[idx];
    if (b == 0) {
        for (int i = t; i < 2 * 512; i += 256) g_ctxnum[i] = 0.f;
        if (t < 2 * 64) g_den[t] = 0.f;
    }
}

// stage a pre-transposed 64x64 matrix into swizzled smem (128 threads)
__device__ __forceinline__ void stage_wt(float* __restrict__ Ws,
                                         const float* __restrict__ gw, int t) {
    const float4* g4 = (const float4*)gw;
#pragma unroll
    for (int i = 0; i < 8; i++) {
        int idx = i * 128 + t;
        float4 v = g4[idx];
        int row = idx >> 4, u = idx & 15;
        *(float4*)(Ws + row * 64 + ((u << 2) ^ swk(row))) = v;
    }
}

// out[c][e] = sum_d A[c][d]*B[e][d], f32x2-paired along d; 8x8 thread tile.
// cg may address rows 0..127 (A); eg rows 0..63 (B).
__device__ __forceinline__ void gemm2(const float* __restrict__ As,
                                      const float* __restrict__ Bs,
                                      int cg, int eg, u64t acc[8][8]) {
#pragma unroll
    for (int i = 0; i < 8; i++)
#pragma unroll
        for (int j = 0; j < 8; j++) acc[i][j] = 0ull;
    const int ka0 = swk(cg), kb0 = swk(eg);   // swk(cg+i) = ka0 ^ (i<<2) since cg%8==0
    const float* Ab = As + cg * 64;
    const float* Bb = Bs + eg * 64;
#pragma unroll 2
    for (int p = 0; p < 32; p++) {
        const int pp = p * 2;
        u64t a[8], b[8];
#pragma unroll
        for (int i = 0; i < 8; i++) a[i] = *(const u64t*)(Ab + i * 64 + (pp ^ ka0 ^ (i << 2)));
#pragma unroll
        for (int j = 0; j < 8; j++) b[j] = *(const u64t*)(Bb + j * 64 + (pp ^ kb0 ^ (j << 2)));
#pragma unroll
        for (int i = 0; i < 8; i++)
#pragma unroll
            for (int j = 0; j < 8; j++)
                FMA2(acc[i][j], a[i], b[j]);
    }
}

__device__ __forceinline__ void load_sb(const float* s, const float* b, int eg,
                                        float sv8[8], float bv8[8]) {
    float4 s0 = *(const float4*)(s + eg), s1 = *(const float4*)(s + eg + 4);
    float4 b0 = *(const float4*)(b + eg), b1 = *(const float4*)(b + eg + 4);
    sv8[0]=s0.x; sv8[1]=s0.y; sv8[2]=s0.z; sv8[3]=s0.w;
    sv8[4]=s1.x; sv8[5]=s1.y; sv8[6]=s1.z; sv8[7]=s1.w;
    bv8[0]=b0.x; bv8[1]=b0.y; bv8[2]=b0.z; bv8[3]=b0.w;
    bv8[4]=b1.x; bv8[5]=b1.y; bv8[6]=b1.z; bv8[7]=b1.w;
}

__global__ void __launch_bounds__(128) passA_kernel(
    const float* __restrict__ x,
    const float* __restrict__ sk, const float* __restrict__ bk,
    const float* __restrict__ sq, const float* __restrict__ bq,
    const float* __restrict__ sv, const float* __restrict__ bv)
{
    extern __shared__ float sm[];
    float* Xt = sm;            // 128 x 64: Xt[token][d]; later V stash (128 rows)
    float* W0 = sm + 8192;     // WqT
    float* W1 = sm + 12288;    // WkT
    float* W2 = sm + 16384;    // WvT
    float* EK = sm + 8192;     // expK stash (128 rows), reuses W0+W1 region
    const int t    = threadIdx.x;
    const int tt   = t & 63;
    const int half = t >> 6;
    const int b    = blockIdx.x;
    const int n    = b >> 11;
    const int hw   = (b & 2047) * 2 + half;
    const size_t xbase = (size_t)n * (64ull * PLANE) + (size_t)hw * 64;

    {   // transpose X: thread t owns token row t (token c = tt of its half)
        const int Kt = swk(t);
#pragma unroll
        for (int u = 0; u < 16; u++) {
            float4 v;
            v.x = x[xbase + (size_t)(u * 4 + 0) * PLANE + tt];
            v.y = x[xbase + (size_t)(u * 4 + 1) * PLANE + tt];
            v.z = x[xbase + (size_t)(u * 4 + 2) * PLANE + tt];
            v.w = x[xbase + (size_t)(u * 4 + 3) * PLANE + tt];
            *(float4*)(Xt + t * 64 + ((u << 2) ^ Kt)) = v;
        }
    }
    stage_wt(W0, g_WT,        t);
    stage_wt(W1, g_WT + 4096, t);
    stage_wt(W2, g_WT + 8192, t);
    __syncthreads();

    const int cgl = (tt & 7) * 8;          // local token group (within half)
    const int cg  = half * 64 + cgl;       // A-row group
    const int eg  = (tt >> 3) * 8;         // channel group = head a = tt>>3
    u64t acc[8][8];

    // ---------------- Q: proj + register softmax + store ----------------
    gemm2(Xt, W0, cg, eg, acc);
    {
        float sv8[8], bv8[8];
        load_sb(sq, bq, eg, sv8, bv8);
        const size_t qb = ((size_t)n * T_TOK + hw) * 64 + eg;
#pragma unroll
        for (int i = 0; i < 8; i++) {
            float q[8];
#pragma unroll
            for (int j = 0; j < 8; j++) {
                float2 f = unpk(acc[i][j]);
                q[j] = lrelu((f.x + f.y) * sv8[j] + bv8[j]);
            }
            float m = q[0];
#pragma unroll
            for (int j = 1; j < 8; j++) m = fmaxf(m, q[j]);
            float s = 0.f;
#pragma unroll
            for (int j = 0; j < 8; j++) { q[j] = __expf(q[j] - m); s += q[j]; }
            float inv = 1.f / s;
            float* dst = g_Q + qb + (size_t)(cgl + i) * PLANE;
            *(float4*)dst       = make_float4(q[0]*inv, q[1]*inv, q[2]*inv, q[3]*inv);
            *(float4*)(dst + 4) = make_float4(q[4]*inv, q[5]*inv, q[6]*inv, q[7]*inv);
        }
    }

    // ---------------- K: proj (reads W1) ----------------
    gemm2(Xt, W1, cg, eg, acc);
    __syncthreads();               // drain all Q/K gemm reads of W0/W1
    {
        float sv8[8], bv8[8];
        load_sb(sk, bk, eg, sv8, bv8);
#pragma unroll
        for (int i = 0; i < 8; i++) {
            int r = cg + i, Kc = swk(r);
            float e8[8];
#pragma unroll
            for (int j = 0; j < 8; j++) {
                float2 f = unpk(acc[i][j]);
                e8[j] = __expf(lrelu((f.x + f.y) * sv8[j] + bv8[j]));
            }
            *(float4*)(EK + r * 64 + (eg ^ Kc))       = make_float4(e8[0], e8[1], e8[2], e8[3]);
            *(float4*)(EK + r * 64 + ((eg + 4) ^ Kc)) = make_float4(e8[4], e8[5], e8[6], e8[7]);
        }
    }

    // ---------------- V: proj (reads Xt, W2) ----------------
    gemm2(Xt, W2, cg, eg, acc);
    __syncthreads();               // drain all V gemm reads of Xt; EK visible
    {
        float sv8[8], bv8[8];
        load_sb(sv, bv, eg, sv8, bv8);
#pragma unroll
        for (int i = 0; i < 8; i++) {
            int r = cg + i, Kc = swk(r);
            float v8[8];
#pragma unroll
            for (int j = 0; j < 8; j++) {
                float2 f = unpk(acc[i][j]);
                v8[j] = lrelu((f.x + f.y) * sv8[j] + bv8[j]);
            }
            *(float4*)(Xt + r * 64 + (eg ^ Kc))       = make_float4(v8[0], v8[1], v8[2], v8[3]);
            *(float4*)(Xt + r * 64 + ((eg + 4) ^ Kc)) = make_float4(v8[4], v8[5], v8[6], v8[7]);
        }
    }
    __syncthreads();

    // ---------------- ctx numerator / denominator ----------------
    {
        const int a2 = tt >> 3;            // thread handles (a,k) = tt, its half's 64 rows
        u64t cacc[4] = {0ull, 0ull, 0ull, 0ull};
        float dsum = 0.f;
#pragma unroll 8
        for (int cc = 0; cc < 64; cc++) {
            int r = half * 64 + cc, Kc = swk(r);
            float ek = EK[r * 64 + (tt ^ Kc)];
            dsum += ek;
            u64t ek2 = pk2(ek, ek);
            const float* vr = Xt + r * 64;
            FMA2(cacc[0], ek2, *(const u64t*)(vr + ((a2 * 8 + 0) ^ Kc)));
            FMA2(cacc[1], ek2, *(const u64t*)(vr + ((a2 * 8 + 2) ^ Kc)));
            FMA2(cacc[2], ek2, *(const u64t*)(vr + ((a2 * 8 + 4) ^ Kc)));
            FMA2(cacc[3], ek2, *(const u64t*)(vr + ((a2 * 8 + 6) ^ Kc)));
        }
        float* dst = g_ctxnum + n * 512 + tt * 8;
#pragma unroll
        for (int m = 0; m < 4; m++) {
            float2 f = unpk(cacc[m]);
            atomicAdd(dst + 2 * m,     f.x);
            atomicAdd(dst + 2 * m + 1, f.y);
        }
        atomicAdd(g_den + n * 64 + tt, dsum);
    }
}

__global__ void __launch_bounds__(128) passC_kernel(
    const float* __restrict__ x,
    const float* __restrict__ sr, const float* __restrict__ br,
    float* __restrict__ out)
{
    extern __shared__ float sm[];
    float* Qs   = sm;            // 128 x 64 Q rows
    float* Ag   = sm + 8192;     // 128 x 64 agg
    float* Ws   = sm + 16384;    // WrT
    float* ctxs = sm + 20480;    // 512
    const int t    = threadIdx.x;
    const int tt   = t & 63;
    const int half = t >> 6;
    const int b    = blockIdx.x;
    const int n    = b >> 11;
    const int hw   = (b & 2047) * 2 + half;
    const int h    = hw >> 6, w = hw & 63;

    stage_wt(Ws, g_WT + 3 * 4096, t);
    for (int g = t; g < 512; g += 128)
        ctxs[g] = g_ctxnum[n * 512 + g] / g_den[n * 64 + (g >> 3)];
    {   // load Q row t: (r,v) = (tt>>3, tt&7), global row R for this half's hw
        int r = tt >> 3, v = tt & 7;
        size_t R = (size_t)r * 32768 + h * 512 + w * 8 + v;
        const float4* src = (const float4*)(g_Q + ((size_t)n * T_TOK + R) * 64);
        const int Kt = swk(t);
#pragma unroll
        for (int u = 0; u < 16; u++) {
            float4 val = src[u];
            *(float4*)(Qs + t * 64 + ((u << 2) ^ Kt)) = val;
        }
    }
    __syncthreads();

    const int cgl = (tt & 7) * 8;
    const int cg  = half * 64 + cgl;
    const int a   = tt >> 3;
    const int eg  = a * 8;

    // ---- agg[c][a*8+v] = sum_v' ctx[a][c>>3][v'] * Q[(c&7)*8+v][a*8+v'] ----
    {
        u64t c2[4];
#pragma unroll
        for (int m = 0; m < 4; m++)
            c2[m] = *(const u64t*)(ctxs + a * 64 + (tt & 7) * 8 + 2 * m);
#pragma unroll
        for (int i = 0; i < 8; i++) {
            float row[8];
#pragma unroll
            for (int v = 0; v < 8; v++) {
                int qr = half * 64 + i * 8 + v, K4 = swk(qr);
                const float* q = Qs + qr * 64;
                u64t acc1 = 0ull;
                FMA2(acc1, c2[0], *(const u64t*)(q + ((eg + 0) ^ K4)));
                FMA2(acc1, c2[1], *(const u64t*)(q + ((eg + 2) ^ K4)));
                FMA2(acc1, c2[2], *(const u64t*)(q + ((eg + 4) ^ K4)));
                FMA2(acc1, c2[3], *(const u64t*)(q + ((eg + 6) ^ K4)));
                float2 f = unpk(acc1);
                row[v] = f.x + f.y;
            }
            int r = cg + i, Kc = swk(r);
            *(float4*)(Ag + r * 64 + (eg ^ Kc))       = make_float4(row[0], row[1], row[2], row[3]);
            *(float4*)(Ag + r * 64 + ((eg + 4) ^ Kc)) = make_float4(row[4], row[5], row[6], row[7]);
        }
    }
    __syncthreads();

    // ---- rep[c][d] = sum_e agg[c][e] * Wr[e][d];  + residual + store ----
    const int dg = (tt >> 3) * 8;
    u64t acc[8][8];
    gemm2(Ag, Ws, cg, dg, acc);
    {
        float sv8[8], bv8[8];
        load_sb(sr, br, dg, sv8, bv8);
        const size_t ob = (size_t)n * (64ull * PLANE) + (size_t)hw * 64;
#pragma unroll
        for (int j = 0; j < 8; j++) {
            int d = dg + j;
            const float* xp = x + ob + (size_t)d * PLANE + cgl;
            float4 x0 = *(const float4*)xp, x1 = *(const float4*)(xp + 4);
            float4 y0, y1;
            float2 f;
            f = unpk(acc[0][j]); y0.x = lrelu((f.x + f.y) * sv8[j] + bv8[j]) + x0.x;
            f = unpk(acc[1][j]); y0.y = lrelu((f.x + f.y) * sv8[j] + bv8[j]) + x0.y;
            f = unpk(acc[2][j]); y0.z = lrelu((f.x + f.y) * sv8[j] + bv8[j]) + x0.z;
            f = unpk(acc[3][j]); y0.w = lrelu((f.x + f.y) * sv8[j] + bv8[j]) + x0.w;
            f = unpk(acc[4][j]); y1.x = lrelu((f.x + f.y) * sv8[j] + bv8[j]) + x1.x;
            f = unpk(acc[5][j]); y1.y = lrelu((f.x + f.y) * sv8[j] + bv8[j]) + x1.y;
            f = unpk(acc[6][j]); y1.z = lrelu((f.x + f.y) * sv8[j] + bv8[j]) + x1.z;
            f = unpk(acc[7][j]); y1.w = lrelu((f.x + f.y) * sv8[j] + bv8[j]) + x1.w;
            float* op = out + ob + (size_t)d * PLANE + cgl;
            *(float4*)op       = y0;
            *(float4*)(op + 4) = y1;
        }
    }
}

extern "C" void kernel_launch(void* const* d_in, const int* in_sizes, int n_in,
                              void* d_out, int out_size) {
    const float* x  = (const float*)d_in[0];
    const float* Wk = (const float*)d_in[1];
    const float* sk = (const float*)d_in[2];
    const float* bk = (const float*)d_in[3];
    const float* Wq = (const float*)d_in[4];
    const float* sq = (const float*)d_in[5];
    const float* bq = (const float*)d_in[6];
    const float* Wv = (const float*)d_in[7];
    const float* sv = (const float*)d_in[8];
    const float* bv = (const float*)d_in[9];
    const float* Wr = (const float*)d_in[10];
    const float* sr = (const float*)d_in[11];
    const float* br = (const float*)d_in[12];
    float* out = (float*)d_out;

    const int smemA = 20480 * 4;   // 81920 B
    const int smemC = 20992 * 4;   // 83968 B
    cudaFuncSetAttribute(passA_kernel, cudaFuncAttributeMaxDynamicSharedMemorySize, smemA);
    cudaFuncSetAttribute(passC_kernel, cudaFuncAttributeMaxDynamicSharedMemorySize, smemC);

    setup_kernel<<<4, 256>>>(Wq, Wk, Wv, Wr);
    passA_kernel<<<4096, 128, smemA>>>(x, sk, bk, sq, bq, sv, bv);
    passC_kernel<<<4096, 128, smemC>>>(x, sr, br, out);
}

// round 7
// speedup vs baseline: 1.0822x; 1.0822x over previous
#include <cuda_runtime.h>
#include <cstdint>

// ---------------------------------------------------------------------------
// EfficientAttention via warp-level mma.sync tf32 (m16n8k8), sm_103-safe PTX.
// N=2, D=64, H=W=64, C=64, HEADS=8, hk=hv=8. token = c*4096 + h*64 + w.
// Per block: 128 tokens (2 hw positions), 128 threads = 4 warps.
// Staged matrices: [row][68] float stride (conflict-free for frag patterns).
// Math identical to verified R1 kernel; GEMMs run on HMMA via mma.sync.
// ---------------------------------------------------------------------------

typedef uint32_t u32;

#define T_TOK 262144
#define PLANE 262144

__device__ float g_Q[(size_t)2 * T_TOK * 64];   // 128 MiB scratch (f32)
__device__ float g_WT[4 * 4096];                // WqT,WkT,WvT,WrT as tf32 bits
__device__ float g_ctxnum[2 * 512];
__device__ float g_den[2 * 64];

__device__ __forceinline__ float lrelu(float y) { return y >= 0.f ? y : 0.2f * y; }
__device__ __forceinline__ u32 f2tf(float f) {
    u32 r; asm("cvt.rna.tf32.f32 %0, %1;" : "=r"(r) : "f"(f)); return r;
}

__device__ __forceinline__ void mma8(float c[4], u32 a0, u32 a1, u32 a2, u32 a3,
                                     u32 b0, u32 b1) {
    asm volatile(
        "mma.sync.aligned.m16n8k8.row.col.f32.tf32.tf32.f32 "
        "{%0,%1,%2,%3}, {%4,%5,%6,%7}, {%8,%9}, {%0,%1,%2,%3};"
        : "+f"(c[0]), "+f"(c[1]), "+f"(c[2]), "+f"(c[3])
        : "r"(a0), "r"(a1), "r"(a2), "r"(a3), "r"(b0), "r"(b1));
}

// out[c][e] = sum_d A[c][d]*B[e][d].  A: [0..127][68] tf32 bits; B: [0..63][68].
// Warp computes rows mbase..mbase+31, all 64 cols. acc[mt][nt][4].
// Frag maps (PTX m16n8k8 tf32): a0=(grp,q) a1=(grp+8,q) a2=(grp,q+4) a3=(grp+8,q+4);
// b0=B(k=q,n=grp), b1=(q+4,grp); c0=(grp,2q) c1=(grp,2q+1) c2=(grp+8,2q) c3=(+1).
__device__ __forceinline__ void warp_gemm(const u32* As, const u32* Bs,
                                          int mbase, int grp, int q,
                                          float acc[2][8][4]) {
#pragma unroll
    for (int mt = 0; mt < 2; mt++)
#pragma unroll
        for (int nt = 0; nt < 8; nt++)
#pragma unroll
            for (int k = 0; k < 4; k++) acc[mt][nt][k] = 0.f;
    const u32* a0p = As + (mbase + grp) * 68 + q;
    const u32* b0p = Bs + grp * 68 + q;
#pragma unroll
    for (int kt = 0; kt < 8; kt++) {
        u32 a[2][4];
#pragma unroll
        for (int mt = 0; mt < 2; mt++) {
            const u32* ap = a0p + mt * (16 * 68) + kt * 8;
            a[mt][0] = ap[0];
            a[mt][1] = ap[8 * 68];
            a[mt][2] = ap[4];
            a[mt][3] = ap[8 * 68 + 4];
        }
        u32 bb[8][2];
#pragma unroll
        for (int nt = 0; nt < 8; nt++) {
            const u32* bp = b0p + nt * (8 * 68) + kt * 8;
            bb[nt][0] = bp[0];
            bb[nt][1] = bp[4];
        }
#pragma unroll
        for (int mt = 0; mt < 2; mt++)
#pragma unroll
            for (int nt = 0; nt < 8; nt++)
                mma8(acc[mt][nt], a[mt][0], a[mt][1], a[mt][2], a[mt][3],
                     bb[nt][0], bb[nt][1]);
    }
}

__global__ void setup_kernel(const float* __restrict__ Wq, const float* __restrict__ Wk,
                             const float* __restrict__ Wv, const float* __restrict__ Wr) {
    int t = threadIdx.x, b = blockIdx.x;
    const float* W = (b == 0) ? Wq : (b == 1) ? Wk : (b == 2) ? Wv : Wr;
    float* dst = g_WT + b * 4096;
    for (int idx = t; idx < 4096; idx += 256) {
        // W[idx] = W[row][col]; store transposed [col][row] as tf32 bits
        dst[(idx & 63) * 64 + (idx >> 6)] = __uint_as_float(f2tf(W[idx]));
    }
    if (b == 0) {
        for (int i = t; i < 1024; i += 256) g_ctxnum[i] = 0.f;
        if (t < 128) g_den[t] = 0.f;
    }
}

// ---------------- passA smem (floats): Xs[0,8704) Ws[8704,21760) SB[21760,22144) ----
// After GEMMs: EK = [8704,17408) (= Ws0+Ws1), VS = [0,8704) (= Xs).
__global__ void __launch_bounds__(128) passA_kernel(
    const float* __restrict__ x,
    const float* __restrict__ sk, const float* __restrict__ bk,
    const float* __restrict__ sq, const float* __restrict__ bq,
    const float* __restrict__ sv, const float* __restrict__ bv)
{
    extern __shared__ float sm[];
    u32* Xs = (u32*)sm;               // [128][68] tf32 bits
    u32* Ws = (u32*)(sm + 8704);      // 3 x [64][68]
    float* EK = sm + 8704;
    float* VS = sm;
    float* SB = sm + 21760;
    const int t = threadIdx.x, lane = t & 31, wid = t >> 5;
    const int grp = lane >> 2, q = lane & 3;
    const int half = t >> 6, tt = t & 63;
    const int b = blockIdx.x, n = b >> 11;
    const int hw0 = (b & 2047) << 1;
    const size_t xb = (size_t)n * (64ull * PLANE) + (size_t)(hw0 + half) * 64;

    // stage X row t (token channel tt of its half), tf32-converted
#pragma unroll
    for (int u = 0; u < 16; u++) {
        uint4 vv;
        vv.x = f2tf(x[xb + (size_t)(4 * u + 0) * PLANE + tt]);
        vv.y = f2tf(x[xb + (size_t)(4 * u + 1) * PLANE + tt]);
        vv.z = f2tf(x[xb + (size_t)(4 * u + 2) * PLANE + tt]);
        vv.w = f2tf(x[xb + (size_t)(4 * u + 3) * PLANE + tt]);
        *(uint4*)(Xs + t * 68 + 4 * u) = vv;
    }
    // stage WqT/WkT/WvT (tf32 bits already)
    {
        const float4* g4 = (const float4*)g_WT;
#pragma unroll
        for (int i = 0; i < 24; i++) {
            int idx = i * 128 + t;                 // 0..3071
            int mat = idx >> 10, rem = idx & 1023;
            int row = rem >> 4, c4 = (rem & 15) << 2;
            float4 v = g4[idx];
            *(float4*)((float*)Ws + mat * 4352 + row * 68 + c4) = v;
        }
    }
    if (t < 64) {
        SB[t]       = sq[t]; SB[64  + t] = bq[t];
        SB[128 + t] = sk[t]; SB[192 + t] = bk[t];
        SB[256 + t] = sv[t]; SB[320 + t] = bv[t];
    }
    __syncthreads();

    const int mbase = wid * 32;
    const int halfr = wid >> 1;
    float acc[2][8][4];

    // ---------------- Q: proj + quad-shuffle softmax -> g_Q ----------------
    warp_gemm(Xs, Ws, mbase, grp, q, acc);
    {
        const size_t qtok0 = (size_t)n * T_TOK + (size_t)(hw0 + halfr);
#pragma unroll
        for (int mt = 0; mt < 2; mt++)
#pragma unroll
        for (int rr = 0; rr < 2; rr++) {
            int row = mbase + mt * 16 + rr * 8 + grp;
            int c = row & 63;
            float* qdst = g_Q + (qtok0 + (size_t)c * 4096) * 64;
#pragma unroll
            for (int nt = 0; nt < 8; nt++) {
                int ch = nt * 8 + 2 * q;
                float y0 = lrelu(acc[mt][nt][rr * 2 + 0] * SB[ch]     + SB[64 + ch]);
                float y1 = lrelu(acc[mt][nt][rr * 2 + 1] * SB[ch + 1] + SB[64 + ch + 1]);
                float m = fmaxf(y0, y1);
                m = fmaxf(m, __shfl_xor_sync(0xffffffffu, m, 1));
                m = fmaxf(m, __shfl_xor_sync(0xffffffffu, m, 2));
                float e0 = __expf(y0 - m), e1 = __expf(y1 - m);
                float s = e0 + e1;
                s += __shfl_xor_sync(0xffffffffu, s, 1);
                s += __shfl_xor_sync(0xffffffffu, s, 2);
                float inv = 1.f / s;
                *(float2*)(qdst + ch) = make_float2(e0 * inv, e1 * inv);
            }
        }
    }

    // ---------------- K: proj -> exp -> EK stash ----------------
    warp_gemm(Xs, Ws + 4352, mbase, grp, q, acc);
    __syncthreads();     // all warps done reading Ws0/Ws1 before EK overwrites
    {
#pragma unroll
        for (int mt = 0; mt < 2; mt++)
#pragma unroll
        for (int rr = 0; rr < 2; rr++) {
            int row = mbase + mt * 16 + rr * 8 + grp;
#pragma unroll
            for (int nt = 0; nt < 8; nt++) {
                int ch = nt * 8 + 2 * q;
                float e0 = __expf(lrelu(acc[mt][nt][rr * 2 + 0] * SB[128 + ch]     + SB[192 + ch]));
                float e1 = __expf(lrelu(acc[mt][nt][rr * 2 + 1] * SB[128 + ch + 1] + SB[192 + ch + 1]));
                *(float2*)(EK + row * 68 + ch) = make_float2(e0, e1);
            }
        }
    }

    // ---------------- V: proj -> VS stash (own rows of Xs region) ----------------
    warp_gemm(Xs, Ws + 2 * 4352, mbase, grp, q, acc);
    {
#pragma unroll
        for (int mt = 0; mt < 2; mt++)
#pragma unroll
        for (int rr = 0; rr < 2; rr++) {
            int row = mbase + mt * 16 + rr * 8 + grp;
#pragma unroll
            for (int nt = 0; nt < 8; nt++) {
                int ch = nt * 8 + 2 * q;
                float v0 = lrelu(acc[mt][nt][rr * 2 + 0] * SB[256 + ch]     + SB[320 + ch]);
                float v1 = lrelu(acc[mt][nt][rr * 2 + 1] * SB[256 + ch + 1] + SB[320 + ch + 1]);
                *(float2*)(VS + row * 68 + ch) = make_float2(v0, v1);
            }
        }
    }
    __syncthreads();

    // ---------------- ctx num/den: thread (half, a=tt>>3, k=tt&7) over 64 rows ----
    {
        const int a8 = (tt >> 3) << 3;
        const int rbase = half << 6;
        float cacc[8] = {0.f, 0.f, 0.f, 0.f, 0.f, 0.f, 0.f, 0.f};
        float dsum = 0.f;
#pragma unroll 4
        for (int rr = 0; rr < 64; rr++) {
            int r = rbase + rr;
            float ek = EK[r * 68 + tt];
            dsum += ek;
            const float* vr = VS + r * 68 + a8;
#pragma unroll
            for (int j = 0; j < 8; j++) cacc[j] += ek * vr[j];
        }
        float* dst = g_ctxnum + n * 512 + tt * 8;
#pragma unroll
        for (int j = 0; j < 8; j++) atomicAdd(dst + j, cacc[j]);
        atomicAdd(g_den + n * 64 + tt, dsum);
    }
}

// -------- passC smem (floats): Ag[0,8704) WrS[8704,13056) Qs[13056,21760)
//          ctx[21760,22272) SBc[22272,22400) --------
__global__ void __launch_bounds__(128) passC_kernel(
    const float* __restrict__ x,
    const float* __restrict__ sr, const float* __restrict__ br,
    float* __restrict__ out)
{
    extern __shared__ float sm[];
    u32* Ag   = (u32*)sm;
    u32* WrS  = (u32*)(sm + 8704);
    float* Qs   = sm + 13056;
    float* ctxs = sm + 21760;
    float* SBc  = sm + 22272;
    const int t = threadIdx.x, lane = t & 31, wid = t >> 5;
    const int grp = lane >> 2, q = lane & 3;
    const int half = t >> 6, tt = t & 63;
    const int b = blockIdx.x, n = b >> 11;
    const int hw0 = (b & 2047) << 1;
    const int hwme = hw0 + half;
    const int h = hwme >> 6, w = hwme & 63;

    {
        const float4* g4 = (const float4*)(g_WT + 3 * 4096);
#pragma unroll
        for (int i = 0; i < 8; i++) {
            int idx = i * 128 + t;
            int row = idx >> 4, c4 = (idx & 15) << 2;
            float4 v = g4[idx];
            *(float4*)((float*)WrS + row * 68 + c4) = v;
        }
    }
    for (int g = t; g < 512; g += 128)
        ctxs[g] = g_ctxnum[n * 512 + g] / g_den[n * 64 + (g >> 3)];
    if (t < 64) { SBc[t] = sr[t]; SBc[64 + t] = br[t]; }
    {   // Q gather: smem row t <- global Q row R (for this half's hw)
        int r = tt >> 3, v = tt & 7;
        size_t R = (size_t)r * 32768 + (size_t)h * 512 + w * 8 + v;
        const float4* src = (const float4*)(g_Q + ((size_t)n * T_TOK + R) * 64);
#pragma unroll
        for (int u = 0; u < 16; u++)
            *(float4*)(Qs + t * 68 + 4 * u) = src[u];
    }
    __syncthreads();

    // ---- agg[c = k*8+i][a*8+v] = sum_vp ctx[a][k][vp] * Qs[i*8+v][a*8+vp] (per half) ----
    {
        const int a = tt >> 3, k = tt & 7;
        float c8[8];
#pragma unroll
        for (int vp = 0; vp < 8; vp++) c8[vp] = ctxs[a * 64 + k * 8 + vp];
#pragma unroll
        for (int i = 0; i < 8; i++) {
            float rv[8];
#pragma unroll
            for (int v = 0; v < 8; v++) {
                const float* qp = Qs + (half * 64 + i * 8 + v) * 68 + a * 8;
                float s = 0.f;
#pragma unroll
                for (int vp = 0; vp < 8; vp++) s += c8[vp] * qp[vp];
                rv[v] = s;
            }
            int R = half * 64 + k * 8 + i;
            uint4 p0, p1;
            p0.x = f2tf(rv[0]); p0.y = f2tf(rv[1]); p0.z = f2tf(rv[2]); p0.w = f2tf(rv[3]);
            p1.x = f2tf(rv[4]); p1.y = f2tf(rv[5]); p1.z = f2tf(rv[6]); p1.w = f2tf(rv[7]);
            *(uint4*)(Ag + R * 68 + a * 8)     = p0;
            *(uint4*)(Ag + R * 68 + a * 8 + 4) = p1;
        }
    }
    __syncthreads();

    // ---- rep = agg @ Wr (MMA), + scale/bias/lrelu + residual ----
    const int mbase = wid * 32, halfr = wid >> 1;
    float acc[2][8][4];
    warp_gemm(Ag, WrS, mbase, grp, q, acc);
    {
        const size_t ob = (size_t)n * (64ull * PLANE) + (size_t)(hw0 + halfr) * 64;
#pragma unroll
        for (int mt = 0; mt < 2; mt++)
#pragma unroll
        for (int rr = 0; rr < 2; rr++) {
            int row = mbase + mt * 16 + rr * 8 + grp;
            int c = row & 63;
#pragma unroll
            for (int nt = 0; nt < 8; nt++) {
#pragma unroll
                for (int j = 0; j < 2; j++) {
                    int d = nt * 8 + 2 * q + j;
                    float yv = lrelu(acc[mt][nt][rr * 2 + j] * SBc[d] + SBc[64 + d]);
                    size_t off = ob + (size_t)d * PLANE + c;
                    out[off] = yv + x[off];
                }
            }
        }
    }
}

extern "C" void kernel_launch(void* const* d_in, const int* in_sizes, int n_in,
                              void* d_out, int out_size) {
    const float* x  = (const float*)d_in[0];
    const float* Wk = (const float*)d_in[1];
    const float* sk = (const float*)d_in[2];
    const float* bk = (const float*)d_in[3];
    const float* Wq = (const float*)d_in[4];
    const float* sq = (const float*)d_in[5];
    const float* bq = (const float*)d_in[6];
    const float* Wv = (const float*)d_in[7];
    const float* sv = (const float*)d_in[8];
    const float* bv = (const float*)d_in[9];
    const float* Wr = (const float*)d_in[10];
    const float* sr = (const float*)d_in[11];
    const float* br = (const float*)d_in[12];
    float* out = (float*)d_out;

    const int smemA = 22144 * 4;   // 88576 B
    const int smemC = 22400 * 4;   // 89600 B
    cudaFuncSetAttribute(passA_kernel, cudaFuncAttributeMaxDynamicSharedMemorySize, smemA);
    cudaFuncSetAttribute(passC_kernel, cudaFuncAttributeMaxDynamicSharedMemorySize, smemC);

    setup_kernel<<<4, 256>>>(Wq, Wk, Wv, Wr);
    passA_kernel<<<4096, 128, smemA>>>(x, sk, bk, sq, bq, sv, bv);
    passC_kernel<<<4096, 128, smemC>>>(x, sr, br, out);
}

// round 8
// speedup vs baseline: 1.2132x; 1.1210x over previous
#include <cuda_runtime.h>
#include <cuda_fp16.h>
#include <cstdint>

// ---------------------------------------------------------------------------
// EfficientAttention via mma.sync m16n8k16 f16 + ldmatrix (sm_103-safe PTX).
// N=2, D=64, H=W=64, C=64, HEADS=8, hk=hv=8. token = c*4096 + h*64 + w.
// Per block: 128 tokens (2 hw), 128 threads = 4 warps, warp m-tile = 32 rows.
// All staged f16 matrices: row = 64 f16 = 8 chunks of 16B; chunk c of row r
// stored at byte r*128 + ((c ^ (r&7))<<4)  (conflict-free for ldmatrix).
// Math identical to R7 (verified); engine: f16 frags via ldmatrix.
// ---------------------------------------------------------------------------

typedef uint32_t u32;

#define T_TOK 262144
#define PLANE 262144

__device__ __half g_Qh[(size_t)2 * T_TOK * 64];   // 64 MiB Q scratch (f16)
__device__ __half g_WTh[4 * 4096];                // WqT,WkT,WvT,WrT f16 [e][d]
__device__ float g_ctxnum[2 * 512];
__device__ float g_den[2 * 64];

__device__ __forceinline__ float lrelu(float y) { return y >= 0.f ? y : 0.2f * y; }
static __device__ __forceinline__ u32 s2u(const void* p) {
    u32 a; asm("{ .reg .u64 t; cvta.to.shared.u64 t, %1; cvt.u32.u64 %0, t; }"
               : "=r"(a) : "l"(p)); return a;
}
__device__ __forceinline__ u32 choff(int r, int c) {
    return (u32)(r * 128 + ((c ^ (r & 7)) << 4));
}

__device__ __forceinline__ void ldmA(u32 addr, u32 r[4]) {
    asm volatile("ldmatrix.sync.aligned.m8n8.x4.shared.b16 {%0,%1,%2,%3}, [%4];"
                 : "=r"(r[0]), "=r"(r[1]), "=r"(r[2]), "=r"(r[3]) : "r"(addr));
}
__device__ __forceinline__ void ldmB(u32 addr, u32 r[2]) {
    asm volatile("ldmatrix.sync.aligned.m8n8.x2.shared.b16 {%0,%1}, [%2];"
                 : "=r"(r[0]), "=r"(r[1]) : "r"(addr));
}
__device__ __forceinline__ void mma16(float c[4], const u32 a[4], const u32 b[2]) {
    asm volatile(
        "mma.sync.aligned.m16n8k16.row.col.f32.f16.f16.f32 "
        "{%0,%1,%2,%3}, {%4,%5,%6,%7}, {%8,%9}, {%0,%1,%2,%3};"
        : "+f"(c[0]), "+f"(c[1]), "+f"(c[2]), "+f"(c[3])
        : "r"(a[0]), "r"(a[1]), "r"(a[2]), "r"(a[3]), "r"(b[0]), "r"(b[1]));
}

// out[c][e] = sum_d A[c][d]*B[e][d]; A rows mbase..mbase+31; B 64 rows; K=64.
__device__ __forceinline__ void wgemm(u32 Ab, u32 Bb, int mbase, int lane,
                                      float acc[2][8][4]) {
#pragma unroll
    for (int mt = 0; mt < 2; mt++)
#pragma unroll
        for (int nt = 0; nt < 8; nt++)
#pragma unroll
            for (int k = 0; k < 4; k++) acc[mt][nt][k] = 0.f;
    const int l7 = lane & 7;
    const int arow0 = mbase + l7 + (((lane >> 3) & 1) << 3);
    const int acs = lane >> 4;              // A chunk select (0/1)
    const int bcs = (lane >> 3) & 1;        // B chunk select
#pragma unroll
    for (int kt = 0; kt < 4; kt++) {
        u32 a[2][4];
#pragma unroll
        for (int mt = 0; mt < 2; mt++)
            ldmA(Ab + choff(arow0 + mt * 16, 2 * kt + acs), a[mt]);
        u32 bb[8][2];
#pragma unroll
        for (int nt = 0; nt < 8; nt++)
            ldmB(Bb + choff(nt * 8 + l7, 2 * kt + bcs), bb[nt]);
#pragma unroll
        for (int mt = 0; mt < 2; mt++)
#pragma unroll
            for (int nt = 0; nt < 8; nt++)
                mma16(acc[mt][nt], a[mt], bb[nt]);
    }
}

__global__ void setup_kernel(const float* __restrict__ Wq, const float* __restrict__ Wk,
                             const float* __restrict__ Wv, const float* __restrict__ Wr) {
    int t = threadIdx.x, b = blockIdx.x;
    const float* W = (b == 0) ? Wq : (b == 1) ? Wk : (b == 2) ? Wv : Wr;
    __half* dst = g_WTh + b * 4096;
    for (int idx = t; idx < 4096; idx += 256)
        dst[(idx & 63) * 64 + (idx >> 6)] = __float2half(W[idx]);   // [e][d]
    if (b == 0) {
        for (int i = t; i < 1024; i += 256) g_ctxnum[i] = 0.f;
        if (t < 128) g_den[t] = 0.f;
    }
}

// -------- passA smem byte map (42496 B static) --------
// XS [0,16384): X tile 128 rows  -> later VS stash
// WS [16384,40960): Ws m at 16384+m*8192 ; EK stash = [16384,32768)
// SB [40960,42496): sq bq sk bk sv bv (6x64 f32)
__global__ void __launch_bounds__(128, 4) passA_kernel(
    const float* __restrict__ x,
    const float* __restrict__ sk, const float* __restrict__ bk,
    const float* __restrict__ sq, const float* __restrict__ bq,
    const float* __restrict__ sv, const float* __restrict__ bv)
{
    static __shared__ __align__(16) char SM[42496];
    const u32 sb = s2u(SM);
    float* SB = (float*)(SM + 40960);
    const int t = threadIdx.x, lane = t & 31, wid = t >> 5;
    const int grp = lane >> 2, q = lane & 3;
    const int half = t >> 6, tt = t & 63;
    const int b = blockIdx.x, n = b >> 11;
    const int hw0 = (b & 2047) << 1;
    const size_t xb = (size_t)n * (64ull * PLANE) + (size_t)(hw0 + half) * 64;

    // stage X row t (f16): chunk u holds d = 8u..8u+7
#pragma unroll
    for (int u = 0; u < 8; u++) {
        float f[8];
#pragma unroll
        for (int j = 0; j < 8; j++)
            f[j] = x[xb + (size_t)(8 * u + j) * PLANE + tt];
        __half2 p[4];
#pragma unroll
        for (int j = 0; j < 4; j++) p[j] = __floats2half2_rn(f[2 * j], f[2 * j + 1]);
        *(uint4*)(SM + choff(t, u)) = *(uint4*)p;
    }
    // stage WqT/WkT/WvT
    {
        const uint4* g4 = (const uint4*)g_WTh;
#pragma unroll
        for (int i = 0; i < 12; i++) {
            int idx = i * 128 + t;               // 0..1535
            int mat = idx >> 9, rem = idx & 511;
            uint4 v = g4[idx];
            *(uint4*)(SM + 16384 + mat * 8192 + choff(rem >> 3, rem & 7)) = v;
        }
    }
    if (t < 64) {
        SB[t]       = sq[t]; SB[64  + t] = bq[t];
        SB[128 + t] = sk[t]; SB[192 + t] = bk[t];
        SB[256 + t] = sv[t]; SB[320 + t] = bv[t];
    }
    __syncthreads();

    const int mbase = wid * 32;
    const int halfr = wid >> 1;
    float acc[2][8][4];

    // ---------------- Q: proj + quad-shuffle softmax -> g_Qh ----------------
    wgemm(sb, sb + 16384, mbase, lane, acc);
    {
        const size_t qtok0 = (size_t)n * T_TOK + (size_t)(hw0 + halfr);
#pragma unroll
        for (int mt = 0; mt < 2; mt++)
#pragma unroll
        for (int rr = 0; rr < 2; rr++) {
            int row = mbase + mt * 16 + rr * 8 + grp;
            int c = row & 63;
            __half* qdst = g_Qh + (qtok0 + (size_t)c * 4096) * 64;
#pragma unroll
            for (int nt = 0; nt < 8; nt++) {
                int ch = nt * 8 + 2 * q;
                float y0 = lrelu(acc[mt][nt][rr * 2 + 0] * SB[ch]     + SB[64 + ch]);
                float y1 = lrelu(acc[mt][nt][rr * 2 + 1] * SB[ch + 1] + SB[64 + ch + 1]);
                float m = fmaxf(y0, y1);
                m = fmaxf(m, __shfl_xor_sync(0xffffffffu, m, 1));
                m = fmaxf(m, __shfl_xor_sync(0xffffffffu, m, 2));
                float e0 = __expf(y0 - m), e1 = __expf(y1 - m);
                float s = e0 + e1;
                s += __shfl_xor_sync(0xffffffffu, s, 1);
                s += __shfl_xor_sync(0xffffffffu, s, 2);
                float inv = 1.f / s;
                *(__half2*)(qdst + ch) = __floats2half2_rn(e0 * inv, e1 * inv);
            }
        }
    }

    // ---------------- K: proj -> exp -> EK stash (f16) ----------------
    wgemm(sb, sb + 16384 + 8192, mbase, lane, acc);
    __syncthreads();     // all warps done reading Ws0/Ws1 before EK overwrites
    {
#pragma unroll
        for (int mt = 0; mt < 2; mt++)
#pragma unroll
        for (int rr = 0; rr < 2; rr++) {
            int row = mbase + mt * 16 + rr * 8 + grp;
#pragma unroll
            for (int nt = 0; nt < 8; nt++) {
                int ch = nt * 8 + 2 * q;
                float e0 = __expf(lrelu(acc[mt][nt][rr * 2 + 0] * SB[128 + ch]     + SB[192 + ch]));
                float e1 = __expf(lrelu(acc[mt][nt][rr * 2 + 1] * SB[128 + ch + 1] + SB[192 + ch + 1]));
                *(__half2*)(SM + 16384 + choff(row, nt) + 4 * q) = __floats2half2_rn(e0, e1);
            }
        }
    }

    // ---------------- V: proj -> VS stash (XS region, own rows) ----------------
    wgemm(sb, sb + 16384 + 16384, mbase, lane, acc);
    {
#pragma unroll
        for (int mt = 0; mt < 2; mt++)
#pragma unroll
        for (int rr = 0; rr < 2; rr++) {
            int row = mbase + mt * 16 + rr * 8 + grp;
#pragma unroll
            for (int nt = 0; nt < 8; nt++) {
                int ch = nt * 8 + 2 * q;
                float v0 = lrelu(acc[mt][nt][rr * 2 + 0] * SB[256 + ch]     + SB[320 + ch]);
                float v1 = lrelu(acc[mt][nt][rr * 2 + 1] * SB[256 + ch + 1] + SB[320 + ch + 1]);
                *(__half2*)(SM + choff(row, nt) + 4 * q) = __floats2half2_rn(v0, v1);
            }
        }
    }
    __syncthreads();

    // ---------------- ctx num/den: thread (half, a=tt>>3, k=tt&7), 64 rows ----
    {
        const int a = tt >> 3, k = tt & 7;
        const int rbase = half << 6;
        float cacc[8] = {0.f, 0.f, 0.f, 0.f, 0.f, 0.f, 0.f, 0.f};
        float dsum = 0.f;
#pragma unroll 4
        for (int rr = 0; rr < 64; rr++) {
            int r = rbase + rr;
            u32 co = choff(r, a);
            float ek = __half2float(*(const __half*)(SM + 16384 + co + 2 * k));
            dsum += ek;
            uint4 v4 = *(const uint4*)(SM + co);
            const __half2* hp = (const __half2*)&v4;
#pragma unroll
            for (int j = 0; j < 4; j++) {
                float2 f = __half22float2(hp[j]);
                cacc[2 * j + 0] += ek * f.x;
                cacc[2 * j + 1] += ek * f.y;
            }
        }
        float* dst = g_ctxnum + n * 512 + tt * 8;
#pragma unroll
        for (int j = 0; j < 8; j++) atomicAdd(dst + j, cacc[j]);
        atomicAdd(g_den + n * 64 + tt, dsum);
    }
}

// -------- passC smem byte map (43520 B static) --------
// AG [0,16384)  WR [16384,24576)  QS [24576,40960)
// CTX [40960,43008) 512 f32      SBC [43008,43520) 128 f32
__global__ void __launch_bounds__(128, 4) passC_kernel(
    const float* __restrict__ x,
    const float* __restrict__ sr, const float* __restrict__ br,
    float* __restrict__ out)
{
    static __shared__ __align__(16) char SM[43520];
    const u32 sb = s2u(SM);
    float* ctxs = (float*)(SM + 40960);
    float* SBc  = (float*)(SM + 43008);
    const int t = threadIdx.x, lane = t & 31, wid = t >> 5;
    const int grp = lane >> 2, q = lane & 3;
    const int half = t >> 6, tt = t & 63;
    const int b = blockIdx.x, n = b >> 11;
    const int hw0 = (b & 2047) << 1;
    const int hwme = hw0 + half;
    const int h = hwme >> 6, w = hwme & 63;

    {   // stage WrT
        const uint4* g4 = (const uint4*)g_WTh + 3 * 512;
#pragma unroll
        for (int i = 0; i < 4; i++) {
            int idx = i * 128 + t;               // 0..511
            uint4 v = g4[idx];
            *(uint4*)(SM + 16384 + choff(idx >> 3, idx & 7)) = v;
        }
    }
    for (int g = t; g < 512; g += 128)
        ctxs[g] = g_ctxnum[n * 512 + g] / g_den[n * 64 + (g >> 3)];
    if (t < 64) { SBc[t] = sr[t]; SBc[64 + t] = br[t]; }
    {   // Q gather: smem row t <- global Q row R (this half's hw)
        int r = tt >> 3, v = tt & 7;
        size_t R = (size_t)r * 32768 + (size_t)h * 512 + w * 8 + v;
        const uint4* src = (const uint4*)(g_Qh + ((size_t)n * T_TOK + R) * 64);
#pragma unroll
        for (int u = 0; u < 8; u++)
            *(uint4*)(SM + 24576 + choff(t, u)) = src[u];
    }
    __syncthreads();

    // ---- agg[c=k*8+i][a*8+v] = sum_vp ctx[a][k][vp]*Q[i*8+v][a*8+vp] -> AG (f16) ----
    {
        const int a = tt >> 3, k = tt & 7;
        float c8[8];
#pragma unroll
        for (int vp = 0; vp < 8; vp++) c8[vp] = ctxs[a * 64 + k * 8 + vp];
#pragma unroll
        for (int i = 0; i < 8; i++) {
            float rv[8];
#pragma unroll
            for (int v = 0; v < 8; v++) {
                int qr = half * 64 + i * 8 + v;
                uint4 q4 = *(const uint4*)(SM + 24576 + choff(qr, a));
                const __half2* hp = (const __half2*)&q4;
                float s = 0.f;
#pragma unroll
                for (int j = 0; j < 4; j++) {
                    float2 f = __half22float2(hp[j]);
                    s += c8[2 * j] * f.x + c8[2 * j + 1] * f.y;
                }
                rv[v] = s;
            }
            int R2 = half * 64 + k * 8 + i;
            __half2 p[4];
#pragma unroll
            for (int j = 0; j < 4; j++) p[j] = __floats2half2_rn(rv[2 * j], rv[2 * j + 1]);
            *(uint4*)(SM + choff(R2, a)) = *(uint4*)p;
        }
    }
    __syncthreads();

    // ---- rep = agg @ Wr (MMA) + scale/bias/lrelu + residual ----
    const int mbase = wid * 32, halfr = wid >> 1;
    float acc[2][8][4];
    wgemm(sb, sb + 16384, mbase, lane, acc);
    {
        const size_t ob = (size_t)n * (64ull * PLANE) + (size_t)(hw0 + halfr) * 64;
#pragma unroll
        for (int mt = 0; mt < 2; mt++)
#pragma unroll
        for (int rr = 0; rr < 2; rr++) {
            int row = mbase + mt * 16 + rr * 8 + grp;
            int c = row & 63;
#pragma unroll
            for (int nt = 0; nt < 8; nt++) {
#pragma unroll
                for (int j = 0; j < 2; j++) {
                    int d = nt * 8 + 2 * q + j;
                    float yv = lrelu(acc[mt][nt][rr * 2 + j] * SBc[d] + SBc[64 + d]);
                    size_t off = ob + (size_t)d * PLANE + c;
                    out[off] = yv + x[off];
                }
            }
        }
    }
}

extern "C" void kernel_launch(void* const* d_in, const int* in_sizes, int n_in,
                              void* d_out, int out_size) {
    const float* x  = (const float*)d_in[0];
    const float* Wk = (const float*)d_in[1];
    const float* sk = (const float*)d_in[2];
    const float* bk = (const float*)d_in[3];
    const float* Wq = (const float*)d_in[4];
    const float* sq = (const float*)d_in[5];
    const float* bq = (const float*)d_in[6];
    const float* Wv = (const float*)d_in[7];
    const float* sv = (const float*)d_in[8];
    const float* bv = (const float*)d_in[9];
    const float* Wr = (const float*)d_in[10];
    const float* sr = (const float*)d_in[11];
    const float* br = (const float*)d_in[12];
    float* out = (float*)d_out;

    setup_kernel<<<4, 256>>>(Wq, Wk, Wv, Wr);
    passA_kernel<<<4096, 128>>>(x, sk, bk, sq, bq, sv, bv);
    passC_kernel<<<4096, 128>>>(x, sr, br, out);
}

// round 9
// speedup vs baseline: 2.8060x; 2.3129x over previous
#include <cuda_runtime.h>
#include <cuda_fp16.h>
#include <cstdint>

// ---------------------------------------------------------------------------
// EfficientAttention: R1 skeleton (256 thr, 8192 blocks, 64-token tiles,
// coalesced Q I/O, smem epilogues, verified ctx/agg math) with the GEMMs
// swapped to f16 mma.sync m16n8k16 + ldmatrix (R8-verified fragment maps).
// N=2, D=64, H=W=64, C=64, HEADS=8. token = c*4096 + h*64 + w.
// f16 tiles: row = 64 halves = 8 chunks of 16B; chunk c of row r at byte
// r*128 + ((c ^ (r&7))<<4)  (conflict-free for ldmatrix).
// ---------------------------------------------------------------------------

typedef uint32_t u32;

#define T_TOK 262144
#define PLANE 262144

__device__ float  g_Q[(size_t)2 * T_TOK * 64];   // 128 MiB Q scratch (f32)
__device__ __half g_WTh[4 * 4096];               // WqT,WkT,WvT,WrT f16 [e][d]
__device__ float  g_ctxnum[2 * 512];
__device__ float  g_den[2 * 64];

__device__ __forceinline__ float lrelu(float y) { return y >= 0.f ? y : 0.2f * y; }
static __device__ __forceinline__ u32 s2u(const void* p) {
    u32 a; asm("{ .reg .u64 t; cvta.to.shared.u64 t, %1; cvt.u32.u64 %0, t; }"
               : "=r"(a) : "l"(p)); return a;
}
__device__ __forceinline__ u32 choff(int r, int c) {
    return (u32)(r * 128 + ((c ^ (r & 7)) << 4));
}
__device__ __forceinline__ void ldmA(u32 addr, u32 r[4]) {
    asm volatile("ldmatrix.sync.aligned.m8n8.x4.shared.b16 {%0,%1,%2,%3}, [%4];"
                 : "=r"(r[0]), "=r"(r[1]), "=r"(r[2]), "=r"(r[3]) : "r"(addr));
}
__device__ __forceinline__ void ldmB(u32 addr, u32 r[2]) {
    asm volatile("ldmatrix.sync.aligned.m8n8.x2.shared.b16 {%0,%1}, [%2];"
                 : "=r"(r[0]), "=r"(r[1]) : "r"(addr));
}
__device__ __forceinline__ void mma16(float c[4], const u32 a[4], const u32 b[2]) {
    asm volatile(
        "mma.sync.aligned.m16n8k16.row.col.f32.f16.f16.f32 "
        "{%0,%1,%2,%3}, {%4,%5,%6,%7}, {%8,%9}, {%0,%1,%2,%3};"
        : "+f"(c[0]), "+f"(c[1]), "+f"(c[2]), "+f"(c[3])
        : "r"(a[0]), "r"(a[1]), "r"(a[2]), "r"(a[3]), "r"(b[0]), "r"(b[1]));
}

__global__ void setup_kernel(const float* __restrict__ Wq, const float* __restrict__ Wk,
                             const float* __restrict__ Wv, const float* __restrict__ Wr) {
    int t = threadIdx.x, b = blockIdx.x;
    const float* W = (b == 0) ? Wq : (b == 1) ? Wk : (b == 2) ? Wv : Wr;
    __half* dst = g_WTh + b * 4096;
    for (int idx = t; idx < 4096; idx += 256)
        dst[(idx & 63) * 64 + (idx >> 6)] = __float2half(W[idx]);   // [e][d]
    if (b == 0) {
        for (int i = t; i < 1024; i += 256) g_ctxnum[i] = 0.f;
        if (t < 128) g_den[t] = 0.f;
    }
}

// -------- passA smem byte map (53760 B static) --------
// Stage phase:   XS f16 [c][d] @0 (8192) ; WS f16 3x @8192 (24576) ; SB @52224
// Epilogue phase (overlays stage): QS f32[64][68] @0, EK @17408, VS @34816
__global__ void __launch_bounds__(256) passA_kernel(
    const float* __restrict__ x,
    const float* __restrict__ sk, const float* __restrict__ bk,
    const float* __restrict__ sq, const float* __restrict__ bq,
    const float* __restrict__ sv, const float* __restrict__ bv)
{
    static __shared__ __align__(16) char SM[53760];
    const u32 sb = s2u(SM);
    float* QS = (float*)SM;
    float* EK = (float*)(SM + 17408);
    float* VS = (float*)(SM + 34816);
    float* SB = (float*)(SM + 52224);
    const int t = threadIdx.x, lane = t & 31, w = t >> 5;
    const int grp = lane >> 2, q = lane & 3, l7 = lane & 7;
    const int b = blockIdx.x, n = b >> 12, hw = b & 4095;
    const size_t xb = (size_t)n * (64ull * PLANE) + (size_t)hw * 64;

    // ---- stage XS f16: row = token c (t&63), 2 d-chunks per thread ----
    {
        const int row = t & 63, u0 = (t >> 6) * 2;
#pragma unroll
        for (int uu = 0; uu < 2; uu++) {
            int u = u0 + uu;
            float f[8];
#pragma unroll
            for (int j = 0; j < 8; j++)
                f[j] = x[xb + (size_t)(8 * u + j) * PLANE + row];
            __half2 p[4];
#pragma unroll
            for (int j = 0; j < 4; j++) p[j] = __floats2half2_rn(f[2 * j], f[2 * j + 1]);
            *(uint4*)(SM + choff(row, u)) = *(uint4*)p;
        }
    }
    // ---- stage WqT/WkT/WvT f16 ----
    {
        const uint4* g4 = (const uint4*)g_WTh;
#pragma unroll
        for (int i = 0; i < 6; i++) {
            int idx = i * 256 + t;                 // 0..1535
            int mat = idx >> 9, rem = idx & 511;
            uint4 v = g4[idx];
            *(uint4*)(SM + 8192 + mat * 8192 + choff(rem >> 3, rem & 7)) = v;
        }
    }
    if (t < 64) {
        SB[t]       = sq[t]; SB[64  + t] = bq[t];
        SB[128 + t] = sk[t]; SB[192 + t] = bk[t];
        SB[256 + t] = sv[t]; SB[320 + t] = bv[t];
    }
    __syncthreads();

    // ---- GEMMs: warp tile = 16 rows (mtile) x 32 cols (nhalf); shared A frags ----
    const int mtile = (w & 3) * 16, nhalf = (w >> 2) * 32;
    const int arow0 = mtile + l7 + (((lane >> 3) & 1) << 3);
    const int acs = lane >> 4, bcs = (lane >> 3) & 1;
    float accQ[4][4], accK[4][4], accV[4][4];
#pragma unroll
    for (int nt = 0; nt < 4; nt++)
#pragma unroll
        for (int k = 0; k < 4; k++) { accQ[nt][k] = 0.f; accK[nt][k] = 0.f; accV[nt][k] = 0.f; }
#pragma unroll
    for (int kt = 0; kt < 4; kt++) {
        u32 a4[4];
        ldmA(sb + choff(arow0, 2 * kt + acs), a4);
#pragma unroll
        for (int nt = 0; nt < 4; nt++) {
            const u32 bo = choff(nhalf + nt * 8 + l7, 2 * kt + bcs);
            u32 b0[2], b1[2], b2[2];
            ldmB(sb + 8192 + bo, b0);
            ldmB(sb + 16384 + bo, b1);
            ldmB(sb + 24576 + bo, b2);
            mma16(accQ[nt], a4, b0);
            mma16(accK[nt], a4, b1);
            mma16(accV[nt], a4, b2);
        }
    }
    __syncthreads();      // all MMAs done; stage regions may be overwritten

    // ---- Q: quad-shuffle softmax -> QS ; K: exp -> EK ; V -> VS ----
#pragma unroll
    for (int rr = 0; rr < 2; rr++) {
        const int row = mtile + rr * 8 + grp;
#pragma unroll
        for (int nt = 0; nt < 4; nt++) {
            const int ch = nhalf + nt * 8 + 2 * q;
            {
                float y0 = lrelu(accQ[nt][rr * 2 + 0] * SB[ch]     + SB[64 + ch]);
                float y1 = lrelu(accQ[nt][rr * 2 + 1] * SB[ch + 1] + SB[64 + ch + 1]);
                float m = fmaxf(y0, y1);
                m = fmaxf(m, __shfl_xor_sync(0xffffffffu, m, 1));
                m = fmaxf(m, __shfl_xor_sync(0xffffffffu, m, 2));
                float e0 = __expf(y0 - m), e1 = __expf(y1 - m);
                float s = e0 + e1;
                s += __shfl_xor_sync(0xffffffffu, s, 1);
                s += __shfl_xor_sync(0xffffffffu, s, 2);
                float inv = 1.f / s;
                *(float2*)(QS + row * 68 + ch) = make_float2(e0 * inv, e1 * inv);
            }
            {
                float e0 = __expf(lrelu(accK[nt][rr * 2 + 0] * SB[128 + ch]     + SB[192 + ch]));
                float e1 = __expf(lrelu(accK[nt][rr * 2 + 1] * SB[128 + ch + 1] + SB[192 + ch + 1]));
                *(float2*)(EK + row * 68 + ch) = make_float2(e0, e1);
            }
            {
                float v0 = lrelu(accV[nt][rr * 2 + 0] * SB[256 + ch]     + SB[320 + ch]);
                float v1 = lrelu(accV[nt][rr * 2 + 1] * SB[256 + ch + 1] + SB[320 + ch + 1]);
                *(float2*)(VS + row * 68 + ch) = make_float2(v0, v1);
            }
        }
    }
    __syncthreads();

    // ---- g_Q write (R1 verbatim: coalesced 256B rows) ----
    {
        const size_t qbase = ((size_t)n * T_TOK + hw) * 64;
#pragma unroll
        for (int i = 0; i < 4; i++) {
            int idx = t + i * 256;
            int c = idx >> 4, c4 = (idx & 15) << 2;
            *(float4*)(g_Q + qbase + (size_t)c * PLANE + c4) = *(const float4*)(QS + c * 68 + c4);
        }
    }

    // ---- ctx numerator/denominator (R1 verbatim) ----
#pragma unroll
    for (int g = t; g < 512; g += 256) {
        int a = g >> 6, k = (g >> 3) & 7, v = g & 7;
        const float* kp = EK + a * 8 + k;
        const float* vp = VS + a * 8 + v;
        float s = 0.f;
#pragma unroll 8
        for (int c = 0; c < 64; c++) s += kp[c * 68] * vp[c * 68];
        atomicAdd(&g_ctxnum[n * 512 + g], s);
    }
    if (t < 64) {
        const float* kp = EK + t;
        float s = 0.f;
#pragma unroll 8
        for (int c = 0; c < 64; c++) s += kp[c * 68];
        atomicAdd(&g_den[n * 64 + t], s);
    }
}

// -------- passC smem byte map (36352 B static) --------
// Qs f32[64][68] @0 (17408) ; WrS f16 @17408 (8192) ; Ag f16 @25600 (8192)
// ctx @33792 (2048) ; SBc @35840 (512)
__global__ void __launch_bounds__(256) passC_kernel(
    const float* __restrict__ x,
    const float* __restrict__ sr, const float* __restrict__ br,
    float* __restrict__ out)
{
    static __shared__ __align__(16) char SM[36352];
    const u32 sb = s2u(SM);
    float* Qs   = (float*)SM;
    float* ctxs = (float*)(SM + 33792);
    float* SBc  = (float*)(SM + 35840);
    const int t = threadIdx.x, lane = t & 31, w = t >> 5;
    const int grp = lane >> 2, q = lane & 3, l7 = lane & 7;
    const int b = blockIdx.x, n = b >> 12, hw = b & 4095;
    const int h = hw >> 6, ww = hw & 63;
    const size_t qn = (size_t)n * T_TOK * 64;

    {   // stage WrS
        const uint4* g4 = (const uint4*)g_WTh + 3 * 512;
#pragma unroll
        for (int i = 0; i < 2; i++) {
            int idx = i * 256 + t;                 // 0..511
            uint4 v = g4[idx];
            *(uint4*)(SM + 17408 + choff(idx >> 3, idx & 7)) = v;
        }
    }
#pragma unroll
    for (int g = t; g < 512; g += 256)
        ctxs[g] = g_ctxnum[n * 512 + g] / g_den[n * 64 + (g >> 3)];
    if (t < 64) { SBc[t] = sr[t]; SBc[64 + t] = br[t]; }
    {   // Q gather (R1 verbatim)
#pragma unroll
        for (int i = 0; i < 4; i++) {
            int idx = t + i * 256;
            int rv = idx >> 4, c4 = (idx & 15) << 2;
            int r = rv >> 3, v = rv & 7;
            size_t R = (size_t)r * 32768 + (size_t)h * 512 + ww * 8 + v;
            *(float4*)(Qs + rv * 68 + c4) = *(const float4*)(g_Q + qn + R * 64 + c4);
        }
    }
    __syncthreads();

    // ---- agg (R1 verbatim math) -> Ag f16 A-tile ----
    {
        const int cg = (t & 15) << 2;
        const int eg = (t >> 4) << 2;
        const int a  = eg >> 3;
#pragma unroll
        for (int i = 0; i < 4; i++) {
            int c = cg + i;
            int k = c >> 3, rr = (c & 7) << 3;
            float4 cx0 = *(const float4*)(ctxs + (a * 8 + k) * 8);
            float4 cx1 = *(const float4*)(ctxs + (a * 8 + k) * 8 + 4);
            float av[4];
#pragma unroll
            for (int j = 0; j < 4; j++) {
                int v = (eg + j) & 7;
                const float* qp = Qs + (rr + v) * 68 + a * 8;
                float4 q0 = *(const float4*)qp;
                float4 q1 = *(const float4*)(qp + 4);
                av[j] = cx0.x * q0.x + cx0.y * q0.y + cx0.z * q0.z + cx0.w * q0.w
                      + cx1.x * q1.x + cx1.y * q1.y + cx1.z * q1.z + cx1.w * q1.w;
            }
            __half2 p0 = __floats2half2_rn(av[0], av[1]);
            __half2 p1 = __floats2half2_rn(av[2], av[3]);
            uint2 pk; pk.x = *(u32*)&p0; pk.y = *(u32*)&p1;
            *(uint2*)(SM + 25600 + choff(c, eg >> 3) + (eg & 7) * 2) = pk;
        }
    }
    __syncthreads();

    // ---- rep = agg @ Wr via MMA ----
    const int mtile = (w & 3) * 16, nhalf = (w >> 2) * 32;
    const int arow0 = mtile + l7 + (((lane >> 3) & 1) << 3);
    const int acs = lane >> 4, bcs = (lane >> 3) & 1;
    float accR[4][4];
#pragma unroll
    for (int nt = 0; nt < 4; nt++)
#pragma unroll
        for (int k = 0; k < 4; k++) accR[nt][k] = 0.f;
#pragma unroll
    for (int kt = 0; kt < 4; kt++) {
        u32 a4[4];
        ldmA(sb + 25600 + choff(arow0, 2 * kt + acs), a4);
#pragma unroll
        for (int nt = 0; nt < 4; nt++) {
            u32 b2[2];
            ldmB(sb + 17408 + choff(nhalf + nt * 8 + l7, 2 * kt + bcs), b2);
            mma16(accR[nt], a4, b2);
        }
    }

    // ---- epilogue: scale/bias/lrelu + residual ----
    {
        const size_t ob = (size_t)n * (64ull * PLANE) + (size_t)hw * 64;
#pragma unroll
        for (int rr = 0; rr < 2; rr++) {
            const int c = mtile + rr * 8 + grp;
#pragma unroll
            for (int nt = 0; nt < 4; nt++) {
#pragma unroll
                for (int j = 0; j < 2; j++) {
                    const int d = nhalf + nt * 8 + 2 * q + j;
                    float yv = lrelu(accR[nt][rr * 2 + j] * SBc[d] + SBc[64 + d]);
                    const size_t off = ob + (size_t)d * PLANE + c;
                    out[off] = yv + x[off];
                }
            }
        }
    }
}

extern "C" void kernel_launch(void* const* d_in, const int* in_sizes, int n_in,
                              void* d_out, int out_size) {
    const float* x  = (const float*)d_in[0];
    const float* Wk = (const float*)d_in[1];
    const float* sk = (const float*)d_in[2];
    const float* bk = (const float*)d_in[3];
    const float* Wq = (const float*)d_in[4];
    const float* sq = (const float*)d_in[5];
    const float* bq = (const float*)d_in[6];
    const float* Wv = (const float*)d_in[7];
    const float* sv = (const float*)d_in[8];
    const float* bv = (const float*)d_in[9];
    const float* Wr = (const float*)d_in[10];
    const float* sr = (const float*)d_in[11];
    const float* br = (const float*)d_in[12];
    float* out = (float*)d_out;

    setup_kernel<<<4, 256>>>(Wq, Wk, Wv, Wr);
    passA_kernel<<<8192, 256>>>(x, sk, bk, sq, bq, sv, bv);
    passC_kernel<<<8192, 256>>>(x, sr, br, out);
}

// round 11
// speedup vs baseline: 2.9123x; 1.0379x over previous
#include <cuda_runtime.h>
#include <cuda_fp16.h>
#include <cstdint>

// ---------------------------------------------------------------------------
// EfficientAttention: R9 structure (256 thr, 8192 blocks, 64-token tiles,
// f16 mma.sync m16n8k16 + ldmatrix, verified ctx/agg math) with the Q
// scratch in f16 (halved global Q traffic).
// N=2, D=64, H=W=64, C=64, HEADS=8. token = c*4096 + h*64 + w.
// f16 MMA tiles: row = 64 halves = 8 chunks of 16B; chunk c of row r at byte
// r*128 + ((c ^ (r&7))<<4)  (conflict-free for ldmatrix).
// ---------------------------------------------------------------------------

typedef uint32_t u32;

#define T_TOK 262144
#define PLANE 262144

__device__ __half g_Qh[(size_t)2 * T_TOK * 64];  // 64 MiB Q scratch (f16)
__device__ __half g_WTh[4 * 4096];               // WqT,WkT,WvT,WrT f16 [e][d]
__device__ float  g_ctxnum[2 * 512];
__device__ float  g_den[2 * 64];

__device__ __forceinline__ float lrelu(float y) { return y >= 0.f ? y : 0.2f * y; }
static __device__ __forceinline__ u32 s2u(const void* p) {
    u32 a; asm("{ .reg .u64 t; cvta.to.shared.u64 t, %1; cvt.u32.u64 %0, t; }"
               : "=r"(a) : "l"(p)); return a;
}
__device__ __forceinline__ u32 choff(int r, int c) {
    return (u32)(r * 128 + ((c ^ (r & 7)) << 4));
}
// 4B-granular swizzled offset for the f16 Q stash (row = token, ch = channel)
__device__ __forceinline__ u32 qoff(int r, int ch) {
    return (u32)(r * 128 + ((2 * ch) ^ ((r & 7) << 4)));
}
__device__ __forceinline__ void ldmA(u32 addr, u32 r[4]) {
    asm volatile("ldmatrix.sync.aligned.m8n8.x4.shared.b16 {%0,%1,%2,%3}, [%4];"
                 : "=r"(r[0]), "=r"(r[1]), "=r"(r[2]), "=r"(r[3]) : "r"(addr));
}
__device__ __forceinline__ void ldmB(u32 addr, u32 r[2]) {
    asm volatile("ldmatrix.sync.aligned.m8n8.x2.shared.b16 {%0,%1}, [%2];"
                 : "=r"(r[0]), "=r"(r[1]) : "r"(addr));
}
__device__ __forceinline__ void mma16(float c[4], const u32 a[4], const u32 b[2]) {
    asm volatile(
        "mma.sync.aligned.m16n8k16.row.col.f32.f16.f16.f32 "
        "{%0,%1,%2,%3}, {%4,%5,%6,%7}, {%8,%9}, {%0,%1,%2,%3};"
        : "+f"(c[0]), "+f"(c[1]), "+f"(c[2]), "+f"(c[3])
        : "r"(a[0]), "r"(a[1]), "r"(a[2]), "r"(a[3]), "r"(b[0]), "r"(b[1]));
}

__global__ void setup_kernel(const float* __restrict__ Wq, const float* __restrict__ Wk,
                             const float* __restrict__ Wv, const float* __restrict__ Wr) {
    __shared__ float T[64 * 65];
    int t = threadIdx.x, b = blockIdx.x;
    const float* W = (b == 0) ? Wq : (b == 1) ? Wk : (b == 2) ? Wv : Wr;
    __half* dst = g_WTh + b * 4096;
    for (int idx = t; idx < 4096; idx += 256)       // W[d][e] -> T[e][d], coalesced read
        T[(idx & 63) * 65 + (idx >> 6)] = W[idx];
    __syncthreads();
    for (int idx = t; idx < 4096; idx += 256)       // coalesced f16 write, cf-free read
        dst[idx] = __float2half(T[idx + (idx >> 6)]);
    if (b == 0) {
        for (int i = t; i < 1024; i += 256) g_ctxnum[i] = 0.f;
        if (t < 128) g_den[t] = 0.f;
    }
}

// -------- passA smem byte map (53760 B static) --------
// Stage phase:   XS f16 [c][d] @0 (8192) ; WS f16 3x @8192 (24576) ; SB @52224
// Epilogue phase: QSh f16 @0 (8192), EK f32 @17408, VS f32 @34816
__global__ void __launch_bounds__(256) passA_kernel(
    const float* __restrict__ x,
    const float* __restrict__ sk, const float* __restrict__ bk,
    const float* __restrict__ sq, const float* __restrict__ bq,
    const float* __restrict__ sv, const float* __restrict__ bv)
{
    static __shared__ __align__(16) char SM[53760];
    const u32 sb = s2u(SM);
    float* EK = (float*)(SM + 17408);
    float* VS = (float*)(SM + 34816);
    float* SB = (float*)(SM + 52224);
    const int t = threadIdx.x, lane = t & 31, w = t >> 5;
    const int grp = lane >> 2, q = lane & 3, l7 = lane & 7;
    const int b = blockIdx.x, n = b >> 12, hw = b & 4095;
    const size_t xb = (size_t)n * (64ull * PLANE) + (size_t)hw * 64;

    // ---- stage XS f16: row = token c (t&63), 2 d-chunks per thread ----
    {
        const int row = t & 63, u0 = (t >> 6) * 2;
#pragma unroll
        for (int uu = 0; uu < 2; uu++) {
            int u = u0 + uu;
            float f[8];
#pragma unroll
            for (int j = 0; j < 8; j++)
                f[j] = x[xb + (size_t)(8 * u + j) * PLANE + row];
            __half2 p[4];
#pragma unroll
            for (int j = 0; j < 4; j++) p[j] = __floats2half2_rn(f[2 * j], f[2 * j + 1]);
            *(uint4*)(SM + choff(row, u)) = *(uint4*)p;
        }
    }
    // ---- stage WqT/WkT/WvT f16 ----
    {
        const uint4* g4 = (const uint4*)g_WTh;
#pragma unroll
        for (int i = 0; i < 6; i++) {
            int idx = i * 256 + t;                 // 0..1535
            int mat = idx >> 9, rem = idx & 511;
            uint4 v = g4[idx];
            *(uint4*)(SM + 8192 + mat * 8192 + choff(rem >> 3, rem & 7)) = v;
        }
    }
    if (t < 64) {
        SB[t]       = sq[t]; SB[64  + t] = bq[t];
        SB[128 + t] = sk[t]; SB[192 + t] = bk[t];
        SB[256 + t] = sv[t]; SB[320 + t] = bv[t];
    }
    __syncthreads();

    // ---- GEMMs: warp tile = 16 rows (mtile) x 32 cols (nhalf); shared A frags ----
    const int mtile = (w & 3) * 16, nhalf = (w >> 2) * 32;
    const int arow0 = mtile + l7 + (((lane >> 3) & 1) << 3);
    const int acs = lane >> 4, bcs = (lane >> 3) & 1;
    float accQ[4][4], accK[4][4], accV[4][4];
#pragma unroll
    for (int nt = 0; nt < 4; nt++)
#pragma unroll
        for (int k = 0; k < 4; k++) { accQ[nt][k] = 0.f; accK[nt][k] = 0.f; accV[nt][k] = 0.f; }
#pragma unroll
    for (int kt = 0; kt < 4; kt++) {
        u32 a4[4];
        ldmA(sb + choff(arow0, 2 * kt + acs), a4);
#pragma unroll
        for (int nt = 0; nt < 4; nt++) {
            const u32 bo = choff(nhalf + nt * 8 + l7, 2 * kt + bcs);
            u32 b0[2], b1[2], b2[2];
            ldmB(sb + 8192 + bo, b0);
            ldmB(sb + 16384 + bo, b1);
            ldmB(sb + 24576 + bo, b2);
            mma16(accQ[nt], a4, b0);
            mma16(accK[nt], a4, b1);
            mma16(accV[nt], a4, b2);
        }
    }
    __syncthreads();      // all MMAs done; stage regions may be overwritten

    // ---- Q: quad-shuffle softmax -> QSh f16 ; K: exp -> EK ; V -> VS ----
#pragma unroll
    for (int rr = 0; rr < 2; rr++) {
        const int row = mtile + rr * 8 + grp;
#pragma unroll
        for (int nt = 0; nt < 4; nt++) {
            const int ch = nhalf + nt * 8 + 2 * q;
            {
                float y0 = lrelu(accQ[nt][rr * 2 + 0] * SB[ch]     + SB[64 + ch]);
                float y1 = lrelu(accQ[nt][rr * 2 + 1] * SB[ch + 1] + SB[64 + ch + 1]);
                float m = fmaxf(y0, y1);
                m = fmaxf(m, __shfl_xor_sync(0xffffffffu, m, 1));
                m = fmaxf(m, __shfl_xor_sync(0xffffffffu, m, 2));
                float e0 = __expf(y0 - m), e1 = __expf(y1 - m);
                float s = e0 + e1;
                s += __shfl_xor_sync(0xffffffffu, s, 1);
                s += __shfl_xor_sync(0xffffffffu, s, 2);
                float inv = 1.f / s;
                *(__half2*)(SM + qoff(row, ch)) = __floats2half2_rn(e0 * inv, e1 * inv);
            }
            {
                float e0 = __expf(lrelu(accK[nt][rr * 2 + 0] * SB[128 + ch]     + SB[192 + ch]));
                float e1 = __expf(lrelu(accK[nt][rr * 2 + 1] * SB[128 + ch + 1] + SB[192 + ch + 1]));
                *(float2*)(EK + row * 68 + ch) = make_float2(e0, e1);
            }
            {
                float v0 = lrelu(accV[nt][rr * 2 + 0] * SB[256 + ch]     + SB[320 + ch]);
                float v1 = lrelu(accV[nt][rr * 2 + 1] * SB[256 + ch + 1] + SB[320 + ch + 1]);
                *(float2*)(VS + row * 68 + ch) = make_float2(v0, v1);
            }
        }
    }
    __syncthreads();

    // ---- g_Qh write: coalesced 128B f16 rows ----
    {
        const size_t qbase = ((size_t)n * T_TOK + hw) * 64;   // halves
#pragma unroll
        for (int i = 0; i < 2; i++) {
            int idx = t + i * 256;                 // 0..511
            int row = idx >> 3, u = idx & 7;
            uint4 v = *(const uint4*)(SM + row * 128 + ((16 * u) ^ ((row & 7) << 4)));
            *(uint4*)(g_Qh + qbase + (size_t)row * PLANE + 8 * u) = v;
        }
    }

    // ---- ctx numerator/denominator (verified R1 math) ----
#pragma unroll
    for (int g = t; g < 512; g += 256) {
        int a = g >> 6, k = (g >> 3) & 7, v = g & 7;
        const float* kp = EK + a * 8 + k;
        const float* vp = VS + a * 8 + v;
        float s = 0.f;
#pragma unroll 8
        for (int c = 0; c < 64; c++) s += kp[c * 68] * vp[c * 68];
        atomicAdd(&g_ctxnum[n * 512 + g], s);
    }
    if (t < 64) {
        const float* kp = EK + t;
        float s = 0.f;
#pragma unroll 8
        for (int c = 0; c < 64; c++) s += kp[c * 68];
        atomicAdd(&g_den[n * 64 + t], s);
    }
}

// -------- passC smem byte map (36352 B static) --------
// Qs f32[64][68] @0 (17408) ; WrS f16 @17408 (8192) ; Ag f16 @25600 (8192)
// ctx @33792 (2048) ; SBc @35840 (512)
__global__ void __launch_bounds__(256) passC_kernel(
    const float* __restrict__ x,
    const float* __restrict__ sr, const float* __restrict__ br,
    float* __restrict__ out)
{
    static __shared__ __align__(16) char SM[36352];
    const u32 sb = s2u(SM);
    float* Qs   = (float*)SM;
    float* ctxs = (float*)(SM + 33792);
    float* SBc  = (float*)(SM + 35840);
    const int t = threadIdx.x, lane = t & 31, w = t >> 5;
    const int grp = lane >> 2, q = lane & 3, l7 = lane & 7;
    const int b = blockIdx.x, n = b >> 12, hw = b & 4095;
    const int h = hw >> 6, ww = hw & 63;
    const size_t qn = (size_t)n * T_TOK * 64;   // halves

    {   // stage WrS
        const uint4* g4 = (const uint4*)g_WTh + 3 * 512;
#pragma unroll
        for (int i = 0; i < 2; i++) {
            int idx = i * 256 + t;                 // 0..511
            uint4 v = g4[idx];
            *(uint4*)(SM + 17408 + choff(idx >> 3, idx & 7)) = v;
        }
    }
#pragma unroll
    for (int g = t; g < 512; g += 256)
        ctxs[g] = g_ctxnum[n * 512 + g] / g_den[n * 64 + (g >> 3)];
    if (t < 64) { SBc[t] = sr[t]; SBc[64 + t] = br[t]; }
    {   // Q gather: f16 global rows -> f32 Qs[rv][68]
#pragma unroll
        for (int i = 0; i < 2; i++) {
            int idx = t + i * 256;                 // 0..511
            int rv = idx >> 3, u = idx & 7;
            int r = rv >> 3, v = rv & 7;
            size_t R = (size_t)r * 32768 + (size_t)h * 512 + ww * 8 + v;
            uint4 q4 = *(const uint4*)(g_Qh + qn + R * 64 + 8 * u);
            const __half2* hp = (const __half2*)&q4;
            float* dst = Qs + rv * 68 + 8 * u;
            float2 f0 = __half22float2(hp[0]), f1 = __half22float2(hp[1]);
            float2 f2 = __half22float2(hp[2]), f3 = __half22float2(hp[3]);
            *(float4*)dst       = make_float4(f0.x, f0.y, f1.x, f1.y);
            *(float4*)(dst + 4) = make_float4(f2.x, f2.y, f3.x, f3.y);
        }
    }
    __syncthreads();

    // ---- agg (verified R1 math) -> Ag f16 A-tile ----
    {
        const int cg = (t & 15) << 2;
        const int eg = (t >> 4) << 2;
        const int a  = eg >> 3;
#pragma unroll
        for (int i = 0; i < 4; i++) {
            int c = cg + i;
            int k = c >> 3, rr = (c & 7) << 3;
            float4 cx0 = *(const float4*)(ctxs + (a * 8 + k) * 8);
            float4 cx1 = *(const float4*)(ctxs + (a * 8 + k) * 8 + 4);
            float av[4];
#pragma unroll
            for (int j = 0; j < 4; j++) {
                int v = (eg + j) & 7;
                const float* qp = Qs + (rr + v) * 68 + a * 8;
                float4 q0 = *(const float4*)qp;
                float4 q1 = *(const float4*)(qp + 4);
                av[j] = cx0.x * q0.x + cx0.y * q0.y + cx0.z * q0.z + cx0.w * q0.w
                      + cx1.x * q1.x + cx1.y * q1.y + cx1.z * q1.z + cx1.w * q1.w;
            }
            __half2 p0 = __floats2half2_rn(av[0], av[1]);
            __half2 p1 = __floats2half2_rn(av[2], av[3]);
            uint2 pk; pk.x = *(u32*)&p0; pk.y = *(u32*)&p1;
            *(uint2*)(SM + 25600 + choff(c, eg >> 3) + (eg & 7) * 2) = pk;
        }
    }
    __syncthreads();

    // ---- rep = agg @ Wr via MMA ----
    const int mtile = (w & 3) * 16, nhalf = (w >> 2) * 32;
    const int arow0 = mtile + l7 + (((lane >> 3) & 1) << 3);
    const int acs = lane >> 4, bcs = (lane >> 3) & 1;
    float accR[4][4];
#pragma unroll
    for (int nt = 0; nt < 4; nt++)
#pragma unroll
        for (int k = 0; k < 4; k++) accR[nt][k] = 0.f;
#pragma unroll
    for (int kt = 0; kt < 4; kt++) {
        u32 a4[4];
        ldmA(sb + 25600 + choff(arow0, 2 * kt + acs), a4);
#pragma unroll
        for (int nt = 0; nt < 4; nt++) {
            u32 b2[2];
            ldmB(sb + 17408 + choff(nhalf + nt * 8 + l7, 2 * kt + bcs), b2);
            mma16(accR[nt], a4, b2);
        }
    }

    // ---- epilogue: scale/bias/lrelu + residual ----
    {
        const size_t ob = (size_t)n * (64ull * PLANE) + (size_t)hw * 64;
#pragma unroll
        for (int rr = 0; rr < 2; rr++) {
            const int c = mtile + rr * 8 + grp;
#pragma unroll
            for (int nt = 0; nt < 4; nt++) {
#pragma unroll
                for (int j = 0; j < 2; j++) {
                    const int d = nhalf + nt * 8 + 2 * q + j;
                    float yv = lrelu(accR[nt][rr * 2 + j] * SBc[d] + SBc[64 + d]);
                    const size_t off = ob + (size_t)d * PLANE + c;
                    out[off] = yv + x[off];
                }
            }
        }
    }
}

extern "C" void kernel_launch(void* const* d_in, const int* in_sizes, int n_in,
                              void* d_out, int out_size) {
    const float* x  = (const float*)d_in[0];
    const float* Wk = (const float*)d_in[1];
    const float* sk = (const float*)d_in[2];
    const float* bk = (const float*)d_in[3];
    const float* Wq = (const float*)d_in[4];
    const float* sq = (const float*)d_in[5];
    const float* bq = (const float*)d_in[6];
    const float* Wv = (const float*)d_in[7];
    const float* sv = (const float*)d_in[8];
    const float* bv = (const float*)d_in[9];
    const float* Wr = (const float*)d_in[10];
    const float* sr = (const float*)d_in[11];
    const float* br = (const float*)d_in[12];
    float* out = (float*)d_out;

    setup_kernel<<<4, 256>>>(Wq, Wk, Wv, Wr);
    passA_kernel<<<8192, 256>>>(x, sk, bk, sq, bq, sv, bv);
    passC_kernel<<<8192, 256>>>(x, sr, br, out);
}